// round 15
// baseline (speedup 1.0000x reference)
#include <cuda_runtime.h>
#include <cstdint>

#define N_NODES 50000
#define N_EDGES 800000
#define DIM 128
#define HEADS 4
#define NEG_SLOPE 0.2f
#define LN_EPS 1e-5f

#define SCAN_BLK 256
#define N_SCAN_BLKS ((N_NODES + SCAN_BLK - 1) / SCAN_BLK)   // 196

// Scratch (device globals: no allocation allowed in kernel_launch)
__device__ __align__(256) float g_xl[N_NODES * DIM];   // 25.6 MB
__device__ __align__(256) float g_xr[N_NODES * DIM];   // 25.6 MB
__device__ int g_deg[N_NODES];
__device__ int g_off[N_NODES];
__device__ int g_cursor[N_NODES];
__device__ int g_bsum[N_SCAN_BLKS];
__device__ int g_csr_src[N_EDGES];
__device__ int g_is64;

__device__ __forceinline__ int load_idx(const void* raw, int pos, int is64) {
    return is64 ? (int)((const long long*)raw)[pos] : ((const int*)raw)[pos];
}

// f32x2 packed helpers (sm_103a FFMA2 — only reachable via PTX)
__device__ __forceinline__ unsigned long long pack_dup(float v) {
    unsigned long long r;
    asm("mov.b64 %0, {%1, %1};" : "=l"(r) : "f"(v));
    return r;
}
__device__ __forceinline__ void fma2(unsigned long long& acc,
                                     unsigned long long a, unsigned long long b) {
    asm("fma.rn.f32x2 %0, %1, %2, %0;" : "+l"(acc) : "l"(a), "l"(b));
}
__device__ __forceinline__ float2 unpack2(unsigned long long v) {
    float lo, hi;
    asm("mov.b64 {%0, %1}, %2;" : "=f"(lo), "=f"(hi) : "l"(v));
    return make_float2(lo, hi);
}

__device__ __forceinline__ unsigned int smem_u32(const void* p) {
    unsigned int a;
    asm("{ .reg .u64 t; cvta.to.shared.u64 t, %1; cvt.u32.u64 %0, t; }"
        : "=r"(a) : "l"(p));
    return a;
}

// ---------------------------------------------------------------------------
// CSR stream: dtype sniff + zero degree array.
// ---------------------------------------------------------------------------
__global__ void prep_kernel(const void* __restrict__ ei_raw) {
    int i = blockIdx.x * blockDim.x + threadIdx.x;
    if (i == 0) {
        const long long* e64 = (const long long*)ei_raw;
        int ok = 1;
        #pragma unroll
        for (int j = 0; j < 16; j++) {
            long long v = e64[j];
            if (v < 0 || v >= N_NODES) ok = 0;
        }
        g_is64 = ok;
    }
    int stride = gridDim.x * blockDim.x;
    for (int j = i; j < N_NODES; j += stride) g_deg[j] = 0;
}

// CSR stream: degree histogram
__global__ void hist_kernel(const void* __restrict__ ei_raw) {
    int is64 = g_is64;
    int i = blockIdx.x * blockDim.x + threadIdx.x;
    int stride = gridDim.x * blockDim.x;
    for (int e = i; e < N_EDGES; e += stride) {
        int d = load_idx(ei_raw, N_EDGES + e, is64);
        atomicAdd(&g_deg[d], 1);
    }
}

// CSR stream: per-block inclusive scan of deg chunk; block total to g_bsum.
__global__ void scan1_kernel() {
    __shared__ int sh[SCAN_BLK];
    int tid = threadIdx.x;
    int i = blockIdx.x * SCAN_BLK + tid;
    int v = (i < N_NODES) ? g_deg[i] : 0;
    sh[tid] = v;
    __syncthreads();
    #pragma unroll
    for (int o = 1; o < SCAN_BLK; o <<= 1) {
        int t = (tid >= o) ? sh[tid - o] : 0;
        __syncthreads();
        sh[tid] += t;
        __syncthreads();
    }
    if (i < N_NODES) g_off[i] = sh[tid];           // inclusive local
    if (tid == SCAN_BLK - 1) g_bsum[blockIdx.x] = sh[tid];
}

// CSR stream: finalize offsets (each block reduces its prefix of block totals)
__global__ void scan3_kernel() {
    __shared__ int sh[SCAN_BLK];
    int tid = threadIdx.x;
    int bid = blockIdx.x;
    sh[tid] = (tid < bid) ? g_bsum[tid] : 0;        // bid <= 196 <= SCAN_BLK
    __syncthreads();
    #pragma unroll
    for (int o = SCAN_BLK / 2; o > 0; o >>= 1) {
        if (tid < o) sh[tid] += sh[tid + o];
        __syncthreads();
    }
    int prefix = sh[0];
    int i = bid * SCAN_BLK + tid;
    if (i < N_NODES) {
        int excl = g_off[i] - g_deg[i] + prefix;
        g_off[i] = excl;
        g_cursor[i] = excl;
    }
}

// CSR stream: fill
__global__ void fill_kernel(const void* __restrict__ ei_raw) {
    int is64 = g_is64;
    int i = blockIdx.x * blockDim.x + threadIdx.x;
    int stride = gridDim.x * blockDim.x;
    for (int e = i; e < N_EDGES; e += stride) {
        int s = load_idx(ei_raw, e, is64);
        int d = load_idx(ei_raw, N_EDGES + e, is64);
        int pos = atomicAdd(&g_cursor[d], 1);
        g_csr_src[pos] = s;
    }
}

// ---------------------------------------------------------------------------
// GEMM stream: xl = x@W_l + b_l ; xr = x@W_r + b_r (R7 version, best scalar).
// ---------------------------------------------------------------------------
__global__ void __launch_bounds__(256, 2)
gemm_kernel(const float* __restrict__ x,
            const float* __restrict__ Wl, const float* __restrict__ bl,
            const float* __restrict__ Wr, const float* __restrict__ br) {
    const int lane = threadIdx.x & 31;
    const int warp = (blockIdx.x * blockDim.x + threadIdx.x) >> 5;
    const int nwarp = (gridDim.x * blockDim.x) >> 5;
    const int NPW = 4;

    float4 bl4 = ((const float4*)bl)[lane];
    float4 br4 = ((const float4*)br)[lane];

    for (int base = warp * NPW; base < N_NODES; base += nwarp * NPW) {
        float4 xv[NPW];
        #pragma unroll
        for (int i = 0; i < NPW; i++) {
            int n = base + i;
            xv[i] = (n < N_NODES) ? ((const float4*)(x + (size_t)n * DIM))[lane]
                                  : make_float4(0.f, 0.f, 0.f, 0.f);
        }
        unsigned long long al2[NPW][2], ar2[NPW][2];
        #pragma unroll
        for (int i = 0; i < NPW; i++) {
            al2[i][0] = 0ull; al2[i][1] = 0ull;
            ar2[i][0] = 0ull; ar2[i][1] = 0ull;
        }

        #pragma unroll
        for (int k4 = 0; k4 < DIM / 4; k4++) {
            #pragma unroll
            for (int c = 0; c < 4; c++) {
                const int k = k4 * 4 + c;
                ulonglong2 wl2 = ((const ulonglong2*)(Wl + (size_t)k * DIM))[lane];
                ulonglong2 wr2 = ((const ulonglong2*)(Wr + (size_t)k * DIM))[lane];
                #pragma unroll
                for (int i = 0; i < NPW; i++) {
                    float comp = (c == 0) ? xv[i].x : (c == 1) ? xv[i].y
                               : (c == 2) ? xv[i].z : xv[i].w;
                    float xk = __shfl_sync(0xffffffffu, comp, k4);
                    unsigned long long xk2 = pack_dup(xk);
                    fma2(al2[i][0], wl2.x, xk2);
                    fma2(al2[i][1], wl2.y, xk2);
                    fma2(ar2[i][0], wr2.x, xk2);
                    fma2(ar2[i][1], wr2.y, xk2);
                }
            }
        }

        #pragma unroll
        for (int i = 0; i < NPW; i++) {
            int n = base + i;
            if (n < N_NODES) {
                float2 l01 = unpack2(al2[i][0]);
                float2 l23 = unpack2(al2[i][1]);
                float2 r01 = unpack2(ar2[i][0]);
                float2 r23 = unpack2(ar2[i][1]);
                float4 ol = make_float4(l01.x + bl4.x, l01.y + bl4.y,
                                        l23.x + bl4.z, l23.y + bl4.w);
                float4 orr = make_float4(r01.x + br4.x, r01.y + br4.y,
                                         r23.x + br4.z, r23.y + br4.w);
                ((float4*)(g_xl + (size_t)n * DIM))[lane] = ol;
                ((float4*)(g_xr + (size_t)n * DIM))[lane] = orr;
            }
        }
    }
}

// ---------------------------------------------------------------------------
// join: fused per-dst softmax-gather + residual + LN.
// Gathers flow through cp.async double-buffered per-warp smem (8 rows x
// 512 B): issue quad q+1, wait quad q, consume from smem. Each lane copies
// and reads only ITS OWN 16 B -> per-thread cp.async self-visibility, no
// syncwarp. Pipeline depth 8 rows at zero register cost (R12's MLP=8 in
// registers spilled). Node-ahead prefetch (R13) retained.
// alpha = exp(e)/sum(exp(e)) equals the reference softmax (max cancels).
// ---------------------------------------------------------------------------
__device__ __forceinline__ float edge_logit(float4 a, float4 xr4, float4 at) {
    float vx = a.x + xr4.x; vx = vx > 0.f ? vx : NEG_SLOPE * vx;
    float vy = a.y + xr4.y; vy = vy > 0.f ? vy : NEG_SLOPE * vy;
    float vz = a.z + xr4.z; vz = vz > 0.f ? vz : NEG_SLOPE * vz;
    float vw = a.w + xr4.w; vw = vw > 0.f ? vw : NEG_SLOPE * vw;
    return vx * at.x + vy * at.y + vz * at.z + vw * at.w;
}

__device__ __forceinline__ void cp16(unsigned int sa, const void* gp) {
    asm volatile("cp.async.cg.shared.global [%0], [%1], 16;"
                 :: "r"(sa), "l"(gp) : "memory");
}

__global__ void __launch_bounds__(256)
fused_edge_kernel(const float* __restrict__ x,
                  const float* __restrict__ att,
                  const float* __restrict__ bias,
                  const float* __restrict__ gamma,
                  const float* __restrict__ beta,
                  float* __restrict__ out) {
    __shared__ __align__(16) char sbuf[8 * 8 * 512];   // 8 warps x 8 rows x 512B
    const int lane = threadIdx.x & 31;
    const int wib = threadIdx.x >> 5;                  // warp in block
    const int warp = (blockIdx.x * blockDim.x + threadIdx.x) >> 5;
    const int nwarp = (gridDim.x * blockDim.x) >> 5;
    const unsigned FULL = 0xffffffffu;

    const unsigned int sb = smem_u32(sbuf) + wib * 4096 + lane * 16;

    float4 at = ((const float4*)att)[lane];
    float4 bi = ((const float4*)bias)[lane];
    float4 ga = ((const float4*)gamma)[lane];
    float4 be = ((const float4*)beta)[lane];

    // prime the prefetch pipeline for the first node
    int pf_beg = 0, pf_deg = 0, pf_src = 0;
    float4 pf_xr = make_float4(0.f, 0.f, 0.f, 0.f);
    if (warp < N_NODES) {
        pf_beg = g_off[warp];
        pf_deg = g_deg[warp];
        pf_xr = ((const float4*)(g_xr + (size_t)warp * DIM))[lane];
        pf_src = (lane < min(pf_deg, 32)) ? g_csr_src[pf_beg + lane] : 0;
    }

    for (int d = warp; d < N_NODES; d += nwarp) {
        const int beg = pf_beg;
        const int deg = pf_deg;
        const int src0 = pf_src;
        const float4 xr4 = pf_xr;

        int dn = d + nwarp;
        if (dn < N_NODES) {
            pf_beg = g_off[dn];
            pf_deg = g_deg[dn];
            pf_xr = ((const float4*)(g_xr + (size_t)dn * DIM))[lane];
            pf_src = (lane < min(pf_deg, 32)) ? g_csr_src[pf_beg + lane] : 0;
        }

        float4 accA = make_float4(0.f, 0.f, 0.f, 0.f);
        float4 accB = make_float4(0.f, 0.f, 0.f, 0.f);
        float denA = 0.f, denB = 0.f;

        for (int base = 0; base < deg; base += 32) {
            int cnt = min(32, deg - base);
            int my_src = (base == 0) ? src0
                        : ((lane < cnt) ? g_csr_src[beg + base + lane] : 0);

            int nq = (cnt + 3) >> 2;   // number of quads

            // prologue: issue quad 0 (clamped indices; masked later)
            #pragma unroll
            for (int u = 0; u < 4; u++) {
                int sl = min(u, cnt - 1);
                int s = __shfl_sync(FULL, my_src, sl);
                cp16(sb + u * 512, (const char*)(g_xl + (size_t)s * DIM) + lane * 16);
            }
            asm volatile("cp.async.commit_group;" ::: "memory");

            for (int q = 0; q < nq; q++) {
                if (q + 1 < nq) {
                    int slot = ((q + 1) & 1) * 4;
                    #pragma unroll
                    for (int u = 0; u < 4; u++) {
                        int sl = min((q + 1) * 4 + u, cnt - 1);
                        int s = __shfl_sync(FULL, my_src, sl);
                        cp16(sb + (slot + u) * 512,
                             (const char*)(g_xl + (size_t)s * DIM) + lane * 16);
                    }
                    asm volatile("cp.async.commit_group;" ::: "memory");
                    asm volatile("cp.async.wait_group 1;" ::: "memory");
                } else {
                    asm volatile("cp.async.wait_group 0;" ::: "memory");
                }

                int slot = (q & 1) * 4;
                float4 a0, a1, a2, a3;
                {
                    const char* p = (const char*)sbuf + wib * 4096 + lane * 16;
                    a0 = *(const float4*)(p + (slot + 0) * 512);
                    a1 = *(const float4*)(p + (slot + 1) * 512);
                    a2 = *(const float4*)(p + (slot + 2) * 512);
                    a3 = *(const float4*)(p + (slot + 3) * 512);
                }

                float p0 = edge_logit(a0, xr4, at);
                float p1 = edge_logit(a1, xr4, at);
                float p2 = edge_logit(a2, xr4, at);
                float p3 = edge_logit(a3, xr4, at);
                #pragma unroll
                for (int off = 4; off > 0; off >>= 1) {
                    p0 += __shfl_xor_sync(FULL, p0, off);
                    p1 += __shfl_xor_sync(FULL, p1, off);
                    p2 += __shfl_xor_sync(FULL, p2, off);
                    p3 += __shfl_xor_sync(FULL, p3, off);
                }
                int j = q * 4;
                float w0 = (j + 0 < cnt) ? __expf(p0) : 0.f;
                float w1 = (j + 1 < cnt) ? __expf(p1) : 0.f;
                float w2 = (j + 2 < cnt) ? __expf(p2) : 0.f;
                float w3 = (j + 3 < cnt) ? __expf(p3) : 0.f;
                denA += w0 + w1;
                denB += w2 + w3;
                accA.x += w0 * a0.x + w1 * a1.x;
                accA.y += w0 * a0.y + w1 * a1.y;
                accA.z += w0 * a0.z + w1 * a1.z;
                accA.w += w0 * a0.w + w1 * a1.w;
                accB.x += w2 * a2.x + w3 * a3.x;
                accB.y += w2 * a2.y + w3 * a3.y;
                accB.z += w2 * a2.z + w3 * a3.z;
                accB.w += w2 * a2.w + w3 * a3.w;
            }
        }

        float den = denA + denB;
        float4 acc = make_float4(accA.x + accB.x, accA.y + accB.y,
                                 accA.z + accB.z, accA.w + accB.w);
        float inv = (den > 0.f) ? __frcp_rn(den) : 0.f;

        float4 xv = ((const float4*)(x + (size_t)d * DIM))[lane];
        float4 o;
        o.x = acc.x * inv + bi.x + xv.x;
        o.y = acc.y * inv + bi.y + xv.y;
        o.z = acc.z * inv + bi.z + xv.z;
        o.w = acc.w * inv + bi.w + xv.w;

        float s = o.x + o.y + o.z + o.w;
        #pragma unroll
        for (int off = 16; off > 0; off >>= 1)
            s += __shfl_xor_sync(FULL, s, off);
        float mu = s * (1.0f / DIM);

        float dx = o.x - mu, dy = o.y - mu, dz = o.z - mu, dw = o.w - mu;
        float q2 = dx * dx + dy * dy + dz * dz + dw * dw;
        #pragma unroll
        for (int off = 16; off > 0; off >>= 1)
            q2 += __shfl_xor_sync(FULL, q2, off);
        float rs = rsqrtf(q2 * (1.0f / DIM) + LN_EPS);

        float4 r;
        r.x = dx * rs * ga.x + be.x;
        r.y = dy * rs * ga.y + be.y;
        r.z = dz * rs * ga.z + be.z;
        r.w = dw * rs * ga.w + be.w;
        ((float4*)(out + (size_t)d * DIM))[lane] = r;
    }
}

extern "C" void kernel_launch(void* const* d_in, const int* in_sizes, int n_in,
                              void* d_out, int out_size) {
    const float* x     = (const float*)d_in[0];
    const void*  ei    = d_in[1];
    const float* Wl    = (const float*)d_in[2];
    const float* bl    = (const float*)d_in[3];
    const float* Wr    = (const float*)d_in[4];
    const float* br    = (const float*)d_in[5];
    const float* att   = (const float*)d_in[6];
    const float* bias  = (const float*)d_in[7];
    const float* gamma = (const float*)d_in[8];
    const float* beta  = (const float*)d_in[9];
    float*       out   = (float*)d_out;

    // Lazily-created side streams/events (host handles only; no device mem).
    static cudaStream_t s_gemm = nullptr, s_csr = nullptr;
    static cudaEvent_t ev_fork = nullptr, ev_gemm = nullptr, ev_csr = nullptr;
    if (!s_gemm) {
        cudaStreamCreateWithFlags(&s_gemm, cudaStreamNonBlocking);
        cudaStreamCreateWithFlags(&s_csr, cudaStreamNonBlocking);
        cudaEventCreateWithFlags(&ev_fork, cudaEventDisableTiming);
        cudaEventCreateWithFlags(&ev_gemm, cudaEventDisableTiming);
        cudaEventCreateWithFlags(&ev_csr, cudaEventDisableTiming);
    }

    // Fork from the default stream (capture-safe event fork/join pattern).
    cudaEventRecord(ev_fork, 0);
    cudaStreamWaitEvent(s_gemm, ev_fork, 0);
    cudaStreamWaitEvent(s_csr, ev_fork, 0);

    // GEMM branch (independent of CSR build): ~90 us
    gemm_kernel<<<1563, 256, 0, s_gemm>>>(x, Wl, bl, Wr, br);

    // CSR branch: ~50 us, runs concurrently with the GEMM
    prep_kernel<<<256, 256, 0, s_csr>>>(ei);
    hist_kernel<<<1024, 256, 0, s_csr>>>(ei);
    scan1_kernel<<<N_SCAN_BLKS, SCAN_BLK, 0, s_csr>>>();
    scan3_kernel<<<N_SCAN_BLKS, SCAN_BLK, 0, s_csr>>>();
    fill_kernel<<<1024, 256, 0, s_csr>>>(ei);

    // Join both branches back onto the default stream.
    cudaEventRecord(ev_gemm, s_gemm);
    cudaEventRecord(ev_csr, s_csr);
    cudaStreamWaitEvent(0, ev_gemm, 0);
    cudaStreamWaitEvent(0, ev_csr, 0);

    fused_edge_kernel<<<6250, 256>>>(x, att, bias, gamma, beta, out);
}

// round 16
// speedup vs baseline: 1.0503x; 1.0503x over previous
#include <cuda_runtime.h>
#include <cstdint>

#define N_NODES 50000
#define N_EDGES 800000
#define DIM 128
#define HEADS 4
#define NEG_SLOPE 0.2f
#define LN_EPS 1e-5f

#define SCAN_BLK 256
#define N_SCAN_BLKS ((N_NODES + SCAN_BLK - 1) / SCAN_BLK)   // 196

// Scratch (device globals: no allocation allowed in kernel_launch)
__device__ __align__(256) float g_xl[N_NODES * DIM];   // 25.6 MB
__device__ __align__(256) float g_xr[N_NODES * DIM];   // 25.6 MB
__device__ int g_deg[N_NODES];
__device__ int g_off[N_NODES];
__device__ int g_cursor[N_NODES];
__device__ int g_bsum[N_SCAN_BLKS];
__device__ int g_csr_src[N_EDGES];
__device__ int g_is64;

__device__ __forceinline__ int load_idx(const void* raw, int pos, int is64) {
    return is64 ? (int)((const long long*)raw)[pos] : ((const int*)raw)[pos];
}

// f32x2 packed helpers (sm_103a FFMA2 — only reachable via PTX)
__device__ __forceinline__ unsigned long long pack_dup(float v) {
    unsigned long long r;
    asm("mov.b64 %0, {%1, %1};" : "=l"(r) : "f"(v));
    return r;
}
__device__ __forceinline__ void fma2(unsigned long long& acc,
                                     unsigned long long a, unsigned long long b) {
    asm("fma.rn.f32x2 %0, %1, %2, %0;" : "+l"(acc) : "l"(a), "l"(b));
}
__device__ __forceinline__ float2 unpack2(unsigned long long v) {
    float lo, hi;
    asm("mov.b64 {%0, %1}, %2;" : "=f"(lo), "=f"(hi) : "l"(v));
    return make_float2(lo, hi);
}

// ---------------------------------------------------------------------------
// CSR stream: dtype sniff + zero degree array.
// ---------------------------------------------------------------------------
__global__ void prep_kernel(const void* __restrict__ ei_raw) {
    int i = blockIdx.x * blockDim.x + threadIdx.x;
    if (i == 0) {
        const long long* e64 = (const long long*)ei_raw;
        int ok = 1;
        #pragma unroll
        for (int j = 0; j < 16; j++) {
            long long v = e64[j];
            if (v < 0 || v >= N_NODES) ok = 0;
        }
        g_is64 = ok;
    }
    int stride = gridDim.x * blockDim.x;
    for (int j = i; j < N_NODES; j += stride) g_deg[j] = 0;
}

// CSR stream: degree histogram
__global__ void hist_kernel(const void* __restrict__ ei_raw) {
    int is64 = g_is64;
    int i = blockIdx.x * blockDim.x + threadIdx.x;
    int stride = gridDim.x * blockDim.x;
    for (int e = i; e < N_EDGES; e += stride) {
        int d = load_idx(ei_raw, N_EDGES + e, is64);
        atomicAdd(&g_deg[d], 1);
    }
}

// CSR stream: per-block inclusive scan of deg chunk; block total to g_bsum.
__global__ void scan1_kernel() {
    __shared__ int sh[SCAN_BLK];
    int tid = threadIdx.x;
    int i = blockIdx.x * SCAN_BLK + tid;
    int v = (i < N_NODES) ? g_deg[i] : 0;
    sh[tid] = v;
    __syncthreads();
    #pragma unroll
    for (int o = 1; o < SCAN_BLK; o <<= 1) {
        int t = (tid >= o) ? sh[tid - o] : 0;
        __syncthreads();
        sh[tid] += t;
        __syncthreads();
    }
    if (i < N_NODES) g_off[i] = sh[tid];           // inclusive local
    if (tid == SCAN_BLK - 1) g_bsum[blockIdx.x] = sh[tid];
}

// CSR stream: finalize offsets (each block reduces its prefix of block totals)
__global__ void scan3_kernel() {
    __shared__ int sh[SCAN_BLK];
    int tid = threadIdx.x;
    int bid = blockIdx.x;
    sh[tid] = (tid < bid) ? g_bsum[tid] : 0;        // bid <= 196 <= SCAN_BLK
    __syncthreads();
    #pragma unroll
    for (int o = SCAN_BLK / 2; o > 0; o >>= 1) {
        if (tid < o) sh[tid] += sh[tid + o];
        __syncthreads();
    }
    int prefix = sh[0];
    int i = bid * SCAN_BLK + tid;
    if (i < N_NODES) {
        int excl = g_off[i] - g_deg[i] + prefix;
        g_off[i] = excl;
        g_cursor[i] = excl;
    }
}

// CSR stream: fill
__global__ void fill_kernel(const void* __restrict__ ei_raw) {
    int is64 = g_is64;
    int i = blockIdx.x * blockDim.x + threadIdx.x;
    int stride = gridDim.x * blockDim.x;
    for (int e = i; e < N_EDGES; e += stride) {
        int s = load_idx(ei_raw, e, is64);
        int d = load_idx(ei_raw, N_EDGES + e, is64);
        int pos = atomicAdd(&g_cursor[d], 1);
        g_csr_src[pos] = s;
    }
}

// ---------------------------------------------------------------------------
// GEMM stream: xl = x@W_l + b_l ; xr = x@W_r + b_r (R7 version, best scalar).
// ---------------------------------------------------------------------------
__global__ void __launch_bounds__(256, 2)
gemm_kernel(const float* __restrict__ x,
            const float* __restrict__ Wl, const float* __restrict__ bl,
            const float* __restrict__ Wr, const float* __restrict__ br) {
    const int lane = threadIdx.x & 31;
    const int warp = (blockIdx.x * blockDim.x + threadIdx.x) >> 5;
    const int nwarp = (gridDim.x * blockDim.x) >> 5;
    const int NPW = 4;

    float4 bl4 = ((const float4*)bl)[lane];
    float4 br4 = ((const float4*)br)[lane];

    for (int base = warp * NPW; base < N_NODES; base += nwarp * NPW) {
        float4 xv[NPW];
        #pragma unroll
        for (int i = 0; i < NPW; i++) {
            int n = base + i;
            xv[i] = (n < N_NODES) ? ((const float4*)(x + (size_t)n * DIM))[lane]
                                  : make_float4(0.f, 0.f, 0.f, 0.f);
        }
        unsigned long long al2[NPW][2], ar2[NPW][2];
        #pragma unroll
        for (int i = 0; i < NPW; i++) {
            al2[i][0] = 0ull; al2[i][1] = 0ull;
            ar2[i][0] = 0ull; ar2[i][1] = 0ull;
        }

        #pragma unroll
        for (int k4 = 0; k4 < DIM / 4; k4++) {
            #pragma unroll
            for (int c = 0; c < 4; c++) {
                const int k = k4 * 4 + c;
                ulonglong2 wl2 = ((const ulonglong2*)(Wl + (size_t)k * DIM))[lane];
                ulonglong2 wr2 = ((const ulonglong2*)(Wr + (size_t)k * DIM))[lane];
                #pragma unroll
                for (int i = 0; i < NPW; i++) {
                    float comp = (c == 0) ? xv[i].x : (c == 1) ? xv[i].y
                               : (c == 2) ? xv[i].z : xv[i].w;
                    float xk = __shfl_sync(0xffffffffu, comp, k4);
                    unsigned long long xk2 = pack_dup(xk);
                    fma2(al2[i][0], wl2.x, xk2);
                    fma2(al2[i][1], wl2.y, xk2);
                    fma2(ar2[i][0], wr2.x, xk2);
                    fma2(ar2[i][1], wr2.y, xk2);
                }
            }
        }

        #pragma unroll
        for (int i = 0; i < NPW; i++) {
            int n = base + i;
            if (n < N_NODES) {
                float2 l01 = unpack2(al2[i][0]);
                float2 l23 = unpack2(al2[i][1]);
                float2 r01 = unpack2(ar2[i][0]);
                float2 r23 = unpack2(ar2[i][1]);
                float4 ol = make_float4(l01.x + bl4.x, l01.y + bl4.y,
                                        l23.x + bl4.z, l23.y + bl4.w);
                float4 orr = make_float4(r01.x + br4.x, r01.y + br4.y,
                                         r23.x + br4.z, r23.y + br4.w);
                ((float4*)(g_xl + (size_t)n * DIM))[lane] = ol;
                ((float4*)(g_xr + (size_t)n * DIM))[lane] = orr;
            }
        }
    }
}

// ---------------------------------------------------------------------------
// join: fused per-dst softmax-gather + residual + LN (R13 inner loop).
// Launched with 12504 warps -> ~4 nodes per warp so the node-ahead prefetch
// ACTUALLY fires (R13/R15 launched 50000 warps = 1 node/warp -> prefetch was
// dead code and every warp paid the full ~700-cycle startup chain).
// alpha = exp(e)/sum(exp(e)) equals the reference softmax (max cancels;
// +1e-16 negligible since the max term contributes exp(0)=1).
// ---------------------------------------------------------------------------
__device__ __forceinline__ float edge_logit(float4 a, float4 xr4, float4 at) {
    float vx = a.x + xr4.x; vx = vx > 0.f ? vx : NEG_SLOPE * vx;
    float vy = a.y + xr4.y; vy = vy > 0.f ? vy : NEG_SLOPE * vy;
    float vz = a.z + xr4.z; vz = vz > 0.f ? vz : NEG_SLOPE * vz;
    float vw = a.w + xr4.w; vw = vw > 0.f ? vw : NEG_SLOPE * vw;
    return vx * at.x + vy * at.y + vz * at.z + vw * at.w;
}

__global__ void fused_edge_kernel(const float* __restrict__ x,
                                  const float* __restrict__ att,
                                  const float* __restrict__ bias,
                                  const float* __restrict__ gamma,
                                  const float* __restrict__ beta,
                                  float* __restrict__ out) {
    const int lane = threadIdx.x & 31;
    const int warp = (blockIdx.x * blockDim.x + threadIdx.x) >> 5;
    const int nwarp = (gridDim.x * blockDim.x) >> 5;
    const unsigned FULL = 0xffffffffu;

    float4 at = ((const float4*)att)[lane];
    float4 bi = ((const float4*)bias)[lane];
    float4 ga = ((const float4*)gamma)[lane];
    float4 be = ((const float4*)beta)[lane];

    // prime the prefetch pipeline for the first node
    int pf_beg = 0, pf_deg = 0, pf_src = 0;
    float4 pf_xr = make_float4(0.f, 0.f, 0.f, 0.f);
    if (warp < N_NODES) {
        pf_beg = g_off[warp];
        pf_deg = g_deg[warp];
        pf_xr = ((const float4*)(g_xr + (size_t)warp * DIM))[lane];
        pf_src = (lane < min(pf_deg, 32)) ? g_csr_src[pf_beg + lane] : 0;
    }

    for (int d = warp; d < N_NODES; d += nwarp) {
        const int beg = pf_beg;
        const int deg = pf_deg;
        const int src0 = pf_src;
        const float4 xr4 = pf_xr;

        // issue next node's prefetches before doing any work on this node
        int dn = d + nwarp;
        if (dn < N_NODES) {
            pf_beg = g_off[dn];
            pf_deg = g_deg[dn];
            pf_xr = ((const float4*)(g_xr + (size_t)dn * DIM))[lane];
            pf_src = (lane < min(pf_deg, 32)) ? g_csr_src[pf_beg + lane] : 0;
        }

        float4 accA = make_float4(0.f, 0.f, 0.f, 0.f);
        float4 accB = make_float4(0.f, 0.f, 0.f, 0.f);
        float denA = 0.f, denB = 0.f;

        for (int base = 0; base < deg; base += 32) {
            int cnt = min(32, deg - base);
            int my_src = (base == 0) ? src0
                        : ((lane < cnt) ? g_csr_src[beg + base + lane] : 0);

            int j = 0;
            for (; j + 4 <= cnt; j += 4) {
                int s0 = __shfl_sync(FULL, my_src, j + 0);
                int s1 = __shfl_sync(FULL, my_src, j + 1);
                int s2 = __shfl_sync(FULL, my_src, j + 2);
                int s3 = __shfl_sync(FULL, my_src, j + 3);
                float4 a0 = ((const float4*)(g_xl + (size_t)s0 * DIM))[lane];
                float4 a1 = ((const float4*)(g_xl + (size_t)s1 * DIM))[lane];
                float4 a2 = ((const float4*)(g_xl + (size_t)s2 * DIM))[lane];
                float4 a3 = ((const float4*)(g_xl + (size_t)s3 * DIM))[lane];

                float p0 = edge_logit(a0, xr4, at);
                float p1 = edge_logit(a1, xr4, at);
                float p2 = edge_logit(a2, xr4, at);
                float p3 = edge_logit(a3, xr4, at);
                #pragma unroll
                for (int off = 4; off > 0; off >>= 1) {
                    p0 += __shfl_xor_sync(FULL, p0, off);
                    p1 += __shfl_xor_sync(FULL, p1, off);
                    p2 += __shfl_xor_sync(FULL, p2, off);
                    p3 += __shfl_xor_sync(FULL, p3, off);
                }
                float w0 = __expf(p0), w1 = __expf(p1);
                float w2 = __expf(p2), w3 = __expf(p3);
                denA += w0 + w1;
                denB += w2 + w3;
                accA.x += w0 * a0.x + w1 * a1.x;
                accA.y += w0 * a0.y + w1 * a1.y;
                accA.z += w0 * a0.z + w1 * a1.z;
                accA.w += w0 * a0.w + w1 * a1.w;
                accB.x += w2 * a2.x + w3 * a3.x;
                accB.y += w2 * a2.y + w3 * a3.y;
                accB.z += w2 * a2.z + w3 * a3.z;
                accB.w += w2 * a2.w + w3 * a3.w;
            }
            for (; j < cnt; j++) {
                int s = __shfl_sync(FULL, my_src, j);
                float4 a = ((const float4*)(g_xl + (size_t)s * DIM))[lane];
                float p = edge_logit(a, xr4, at);
                #pragma unroll
                for (int off = 4; off > 0; off >>= 1)
                    p += __shfl_xor_sync(FULL, p, off);
                float w = __expf(p);
                denA += w;
                accA.x += w * a.x;
                accA.y += w * a.y;
                accA.z += w * a.z;
                accA.w += w * a.w;
            }
        }

        float den = denA + denB;
        float4 acc = make_float4(accA.x + accB.x, accA.y + accB.y,
                                 accA.z + accB.z, accA.w + accB.w);
        float inv = (den > 0.f) ? __frcp_rn(den) : 0.f;

        float4 xv = ((const float4*)(x + (size_t)d * DIM))[lane];
        float4 o;
        o.x = acc.x * inv + bi.x + xv.x;
        o.y = acc.y * inv + bi.y + xv.y;
        o.z = acc.z * inv + bi.z + xv.z;
        o.w = acc.w * inv + bi.w + xv.w;

        float s = o.x + o.y + o.z + o.w;
        #pragma unroll
        for (int off = 16; off > 0; off >>= 1)
            s += __shfl_xor_sync(FULL, s, off);
        float mu = s * (1.0f / DIM);

        float dx = o.x - mu, dy = o.y - mu, dz = o.z - mu, dw = o.w - mu;
        float q = dx * dx + dy * dy + dz * dz + dw * dw;
        #pragma unroll
        for (int off = 16; off > 0; off >>= 1)
            q += __shfl_xor_sync(FULL, q, off);
        float rs = rsqrtf(q * (1.0f / DIM) + LN_EPS);

        float4 r;
        r.x = dx * rs * ga.x + be.x;
        r.y = dy * rs * ga.y + be.y;
        r.z = dz * rs * ga.z + be.z;
        r.w = dw * rs * ga.w + be.w;
        ((float4*)(out + (size_t)d * DIM))[lane] = r;
    }
}

extern "C" void kernel_launch(void* const* d_in, const int* in_sizes, int n_in,
                              void* d_out, int out_size) {
    const float* x     = (const float*)d_in[0];
    const void*  ei    = d_in[1];
    const float* Wl    = (const float*)d_in[2];
    const float* bl    = (const float*)d_in[3];
    const float* Wr    = (const float*)d_in[4];
    const float* br    = (const float*)d_in[5];
    const float* att   = (const float*)d_in[6];
    const float* bias  = (const float*)d_in[7];
    const float* gamma = (const float*)d_in[8];
    const float* beta  = (const float*)d_in[9];
    float*       out   = (float*)d_out;

    // Lazily-created side streams/events (host handles only; no device mem).
    static cudaStream_t s_gemm = nullptr, s_csr = nullptr;
    static cudaEvent_t ev_fork = nullptr, ev_gemm = nullptr, ev_csr = nullptr;
    if (!s_gemm) {
        cudaStreamCreateWithFlags(&s_gemm, cudaStreamNonBlocking);
        cudaStreamCreateWithFlags(&s_csr, cudaStreamNonBlocking);
        cudaEventCreateWithFlags(&ev_fork, cudaEventDisableTiming);
        cudaEventCreateWithFlags(&ev_gemm, cudaEventDisableTiming);
        cudaEventCreateWithFlags(&ev_csr, cudaEventDisableTiming);
    }

    // Fork from the default stream (capture-safe event fork/join pattern).
    cudaEventRecord(ev_fork, 0);
    cudaStreamWaitEvent(s_gemm, ev_fork, 0);
    cudaStreamWaitEvent(s_csr, ev_fork, 0);

    // GEMM branch (independent of CSR build): ~90 us
    gemm_kernel<<<1563, 256, 0, s_gemm>>>(x, Wl, bl, Wr, br);

    // CSR branch: ~50 us, runs concurrently with the GEMM
    prep_kernel<<<256, 256, 0, s_csr>>>(ei);
    hist_kernel<<<1024, 256, 0, s_csr>>>(ei);
    scan1_kernel<<<N_SCAN_BLKS, SCAN_BLK, 0, s_csr>>>();
    scan3_kernel<<<N_SCAN_BLKS, SCAN_BLK, 0, s_csr>>>();
    fill_kernel<<<1024, 256, 0, s_csr>>>(ei);

    // Join both branches back onto the default stream.
    cudaEventRecord(ev_gemm, s_gemm);
    cudaEventRecord(ev_csr, s_csr);
    cudaStreamWaitEvent(0, ev_gemm, 0);
    cudaStreamWaitEvent(0, ev_csr, 0);

    // 1563 blocks x 8 warps = 12504 warps -> ~4 nodes/warp (prefetch active)
    fused_edge_kernel<<<1563, 256>>>(x, att, bias, gamma, beta, out);
}